// round 14
// baseline (speedup 1.0000x reference)
#include <cuda_runtime.h>
#include <cuda_fp16.h>
#include <math.h>

typedef unsigned long long ull;
typedef unsigned int uint;

// ---------------- problem constants ----------------
#define NNODE 200
#define IMGF  2048
#define HD1   512
#define HD2   256
#define NCH   1024
#define NEDGE 39800
#define TE    64
#define EBLK  622

// ---------------- f32x2 helpers ----------------
__device__ __forceinline__ ull pack2(float a) {
    ull r; asm("mov.b64 %0,{%1,%1};" : "=l"(r) : "f"(a)); return r;
}
__device__ __forceinline__ void ffma2(ull& acc, ull a, ull b) {
    asm("fma.rn.f32x2 %0,%1,%2,%0;" : "+l"(acc) : "l"(a), "l"(b));
}
__device__ __forceinline__ float2 unpk(ull v) {
    float2 r; asm("mov.b64 {%0,%1},%2;" : "=f"(r.x), "=f"(r.y) : "l"(v)); return r;
}

// ---------------- device scratch ----------------
// M is atomic-accumulated and re-zeroed by k_msgvec each execution
// (device globals start zeroed; invariant holds across graph replays).
// x is fully overwritten by k_fused每 execution (no zero needed).
#define OFF_X    0
#define OFF_M    (OFF_X + NNODE*NCH)
#define OFF_P    (OFF_M + NNODE*512)
#define OFF_Q    (OFF_P + NNODE*256)
#define SCR_TOTAL (OFF_Q + NNODE*256)
__device__ float g_scr[SCR_TOTAL];
__device__ __half g_wt[64 * 256];       // we2^T fp16 [n][k] for edge kernel

__device__ __forceinline__ uint smem_u32(const void* p) {
    uint a;
    asm("{ .reg .u64 t; cvta.to.shared.u64 t, %1; cvt.u32.u64 %0, t; }"
        : "=r"(a) : "l"(p));
    return a;
}

// ---------------- fused node MLP: roi -> h1 -> h2 -> x, one kernel ----------
// 13 blocks x 16 rows, 256 threads (8 warps). All GEMMs via mma.m16n8k16.
// Weights staged fp32->fp16 k-major; B frags via ldmatrix.x2.trans.
// smem halfs: sB[64][520] | sA[16][72] | sH1[16][520] | sH2[16][264]
#define SB_H  (64 * 520)
#define SA_H  (16 * 72)
#define SH1_H (16 * 520)
#define SH2_H (16 * 264)
#define FUSED_SMEM ((SB_H + SA_H + SH1_H + SH2_H) * 2)

__global__ void __launch_bounds__(256) k_fused(
    const float* __restrict__ roi,
    const float* __restrict__ w1, const float* __restrict__ b1,
    const float* __restrict__ w2, const float* __restrict__ b2,
    const float* __restrict__ w3, const float* __restrict__ b3,
    float* __restrict__ xo) {
    extern __shared__ __half sdyn[];
    __half* sB  = sdyn;
    __half* sA  = sdyn + SB_H;
    __half* sH1 = sA + SA_H;
    __half* sH2 = sH1 + SH1_H;

    const int t = threadIdx.x, wid = t >> 5, lane = t & 31;
    const int m0 = blockIdx.x * 16;
    const uint sBb = smem_u32(sB), sAb = smem_u32(sA);
    const uint sH1b = smem_u32(sH1), sH2b = smem_u32(sH2);
    const int aj = lane & 7, ag = lane >> 3;
    const uint arow = (uint)((ag & 1) * 8 + aj);
    const uint acol = (uint)((ag >> 1) * 16);
    const int kr16 = lane & 15;
    const int r = lane >> 2, c2 = (lane & 3) * 2;

    // ================= Layer 1: h1[16][512] = roi @ w1 =================
    {
        float D[8][4];
        #pragma unroll
        for (int nf = 0; nf < 8; ++nf)
            #pragma unroll
            for (int i = 0; i < 4; ++i) D[nf][i] = 0.f;

        for (int k0 = 0; k0 < IMGF; k0 += 64) {
            {   // stage A: roi[m0..+16][k0..+64] fp32 -> fp16
                int row = t >> 4, c4 = (t & 15) * 4;
                float4 v = make_float4(0.f, 0.f, 0.f, 0.f);
                if (m0 + row < NNODE)
                    v = *(const float4*)(roi + (size_t)(m0 + row) * IMGF + k0 + c4);
                __half2* p = (__half2*)(sA + row * 72 + c4);
                p[0] = __floats2half2_rn(v.x, v.y);
                p[1] = __floats2half2_rn(v.z, v.w);
            }
            // stage B: w1[k0..+64][0..512] fp32 -> fp16 (k-major, linear)
            #pragma unroll 8
            for (int i = 0; i < 32; ++i) {
                int e4 = i * 256 + t;
                int kr = e4 >> 7, nc4 = (e4 & 127) * 4;
                float4 v = *(const float4*)(w1 + (size_t)(k0 + kr) * HD1 + nc4);
                __half2* p = (__half2*)(sB + kr * 520 + nc4);
                p[0] = __floats2half2_rn(v.x, v.y);
                p[1] = __floats2half2_rn(v.z, v.w);
            }
            __syncthreads();
            #pragma unroll
            for (int ks = 0; ks < 4; ++ks) {
                uint a[4];
                uint addr = sAb + arow * 144 + (uint)(ks * 32) + acol;
                asm volatile("ldmatrix.sync.aligned.m8n8.x4.shared.b16 "
                             "{%0,%1,%2,%3}, [%4];"
                             : "=r"(a[0]), "=r"(a[1]), "=r"(a[2]), "=r"(a[3])
                             : "r"(addr));
                #pragma unroll
                for (int nf = 0; nf < 8; ++nf) {
                    uint b0, b1v;
                    uint baddr = sBb + (uint)((ks * 16 + kr16) * 1040
                                              + (wid * 64 + nf * 8) * 2);
                    asm volatile("ldmatrix.sync.aligned.m8n8.x2.trans.shared.b16 "
                                 "{%0,%1}, [%2];" : "=r"(b0), "=r"(b1v) : "r"(baddr));
                    asm volatile(
                        "mma.sync.aligned.m16n8k16.row.col.f32.f16.f16.f32 "
                        "{%0,%1,%2,%3}, {%4,%5,%6,%7}, {%8,%9}, {%0,%1,%2,%3};"
                        : "+f"(D[nf][0]), "+f"(D[nf][1]), "+f"(D[nf][2]), "+f"(D[nf][3])
                        : "r"(a[0]), "r"(a[1]), "r"(a[2]), "r"(a[3]),
                          "r"(b0), "r"(b1v));
                }
            }
            __syncthreads();
        }
        // epilogue: +b1, relu, fp16 -> sH1
        #pragma unroll
        for (int nf = 0; nf < 8; ++nf) {
            int n = wid * 64 + nf * 8 + c2;
            float bb0 = b1[n], bb1 = b1[n + 1];
            *(__half2*)(sH1 + r * 520 + n) =
                __floats2half2_rn(fmaxf(D[nf][0] + bb0, 0.f), fmaxf(D[nf][1] + bb1, 0.f));
            *(__half2*)(sH1 + (r + 8) * 520 + n) =
                __floats2half2_rn(fmaxf(D[nf][2] + bb0, 0.f), fmaxf(D[nf][3] + bb1, 0.f));
        }
        __syncthreads();
    }

    // ================= Layer 2: h2[16][256] = h1 @ w2 =================
    {
        float D[4][4];
        #pragma unroll
        for (int nf = 0; nf < 4; ++nf)
            #pragma unroll
            for (int i = 0; i < 4; ++i) D[nf][i] = 0.f;

        for (int k0 = 0; k0 < HD1; k0 += 64) {
            #pragma unroll 8
            for (int i = 0; i < 16; ++i) {    // stage w2[k0..+64][0..256]
                int e4 = i * 256 + t;
                int kr = e4 >> 6, nc4 = (e4 & 63) * 4;
                float4 v = *(const float4*)(w2 + (size_t)(k0 + kr) * HD2 + nc4);
                __half2* p = (__half2*)(sB + kr * 520 + nc4);
                p[0] = __floats2half2_rn(v.x, v.y);
                p[1] = __floats2half2_rn(v.z, v.w);
            }
            __syncthreads();
            #pragma unroll
            for (int ks = 0; ks < 4; ++ks) {
                uint a[4];
                uint addr = sH1b + arow * 1040 + (uint)((k0 + ks * 16) * 2) + acol;
                asm volatile("ldmatrix.sync.aligned.m8n8.x4.shared.b16 "
                             "{%0,%1,%2,%3}, [%4];"
                             : "=r"(a[0]), "=r"(a[1]), "=r"(a[2]), "=r"(a[3])
                             : "r"(addr));
                #pragma unroll
                for (int nf = 0; nf < 4; ++nf) {
                    uint b0, b1v;
                    uint baddr = sBb + (uint)((ks * 16 + kr16) * 1040
                                              + (wid * 32 + nf * 8) * 2);
                    asm volatile("ldmatrix.sync.aligned.m8n8.x2.trans.shared.b16 "
                                 "{%0,%1}, [%2];" : "=r"(b0), "=r"(b1v) : "r"(baddr));
                    asm volatile(
                        "mma.sync.aligned.m16n8k16.row.col.f32.f16.f16.f32 "
                        "{%0,%1,%2,%3}, {%4,%5,%6,%7}, {%8,%9}, {%0,%1,%2,%3};"
                        : "+f"(D[nf][0]), "+f"(D[nf][1]), "+f"(D[nf][2]), "+f"(D[nf][3])
                        : "r"(a[0]), "r"(a[1]), "r"(a[2]), "r"(a[3]),
                          "r"(b0), "r"(b1v));
                }
            }
            __syncthreads();
        }
        #pragma unroll
        for (int nf = 0; nf < 4; ++nf) {       // +b2, relu, fp16 -> sH2
            int n = wid * 32 + nf * 8 + c2;
            float bb0 = b2[n], bb1 = b2[n + 1];
            *(__half2*)(sH2 + r * 264 + n) =
                __floats2half2_rn(fmaxf(D[nf][0] + bb0, 0.f), fmaxf(D[nf][1] + bb1, 0.f));
            *(__half2*)(sH2 + (r + 8) * 264 + n) =
                __floats2half2_rn(fmaxf(D[nf][2] + bb0, 0.f), fmaxf(D[nf][3] + bb1, 0.f));
        }
        __syncthreads();
    }

    // ================= Layer 3: x[16][1024] = h2 @ w3 + b3 (no relu) ======
    for (int nh = 0; nh < 2; ++nh) {
        float D[8][4];
        #pragma unroll
        for (int nf = 0; nf < 8; ++nf)
            #pragma unroll
            for (int i = 0; i < 4; ++i) D[nf][i] = 0.f;

        for (int k0 = 0; k0 < HD2; k0 += 64) {
            #pragma unroll 8
            for (int i = 0; i < 32; ++i) {    // stage w3[k0..+64][nh*512..+512]
                int e4 = i * 256 + t;
                int kr = e4 >> 7, nc4 = (e4 & 127) * 4;
                float4 v = *(const float4*)(w3 + (size_t)(k0 + kr) * NCH + nh * 512 + nc4);
                __half2* p = (__half2*)(sB + kr * 520 + nc4);
                p[0] = __floats2half2_rn(v.x, v.y);
                p[1] = __floats2half2_rn(v.z, v.w);
            }
            __syncthreads();
            #pragma unroll
            for (int ks = 0; ks < 4; ++ks) {
                uint a[4];
                uint addr = sH2b + arow * 528 + (uint)((k0 + ks * 16) * 2) + acol;
                asm volatile("ldmatrix.sync.aligned.m8n8.x4.shared.b16 "
                             "{%0,%1,%2,%3}, [%4];"
                             : "=r"(a[0]), "=r"(a[1]), "=r"(a[2]), "=r"(a[3])
                             : "r"(addr));
                #pragma unroll
                for (int nf = 0; nf < 8; ++nf) {
                    uint b0, b1v;
                    uint baddr = sBb + (uint)((ks * 16 + kr16) * 1040
                                              + (wid * 64 + nf * 8) * 2);
                    asm volatile("ldmatrix.sync.aligned.m8n8.x2.trans.shared.b16 "
                                 "{%0,%1}, [%2];" : "=r"(b0), "=r"(b1v) : "r"(baddr));
                    asm volatile(
                        "mma.sync.aligned.m16n8k16.row.col.f32.f16.f16.f32 "
                        "{%0,%1,%2,%3}, {%4,%5,%6,%7}, {%8,%9}, {%0,%1,%2,%3};"
                        : "+f"(D[nf][0]), "+f"(D[nf][1]), "+f"(D[nf][2]), "+f"(D[nf][3])
                        : "r"(a[0]), "r"(a[1]), "r"(a[2]), "r"(a[3]),
                          "r"(b0), "r"(b1v));
                }
            }
            __syncthreads();
        }
        // writeout x fp32 (+b3, no relu)
        int row0 = m0 + r, row1 = m0 + r + 8;
        #pragma unroll
        for (int nf = 0; nf < 8; ++nf) {
            int n = nh * 512 + wid * 64 + nf * 8 + c2;
            float bb0 = b3[n], bb1 = b3[n + 1];
            if (row0 < NNODE) {
                xo[(size_t)row0 * NCH + n] = D[nf][0] + bb0;
                xo[(size_t)row0 * NCH + n + 1] = D[nf][1] + bb1;
            }
            if (row1 < NNODE) {
                xo[(size_t)row1 * NCH + n] = D[nf][2] + bb0;
                xo[(size_t)row1 * NCH + n + 1] = D[nf][3] + bb1;
            }
        }
        __syncthreads();
    }
}

// P/Q precompute + we2^T fp16 conversion
__global__ void k_pq(const float* __restrict__ bbox, const float* __restrict__ dirs,
                     const float* __restrict__ we1, const float* __restrict__ we2,
                     float* __restrict__ P, float* __restrict__ Q) {
    __shared__ float a[8];
    int n = blockIdx.y, j = blockIdx.x * 128 + threadIdx.x;
    if (threadIdx.x < 8) {
        int c = threadIdx.x;
        a[c] = (c < 4) ? bbox[n * 4 + c] * (1.0f / 1024.0f) : dirs[n * 4 + c - 4];
    }
    if (blockIdx.x == 0 && blockIdx.y < 8) {
        int base = (blockIdx.y * 128 + threadIdx.x) * 16;
        #pragma unroll
        for (int i = 0; i < 16; ++i) {
            int m = base + i;
            int nn = m >> 8, k = m & 255;
            g_wt[m] = __float2half(we2[k * 64 + nn]);
        }
    }
    __syncthreads();
    float p = 0.f, q = 0.f;
    #pragma unroll
    for (int c = 0; c < 8; ++c) {
        p += a[c] * we1[c * 256 + j];
        q += a[c] * we1[(c + 8) * 256 + j];
    }
    P[n * 256 + j] = p;
    Q[n * 256 + j] = q;
}

// ---------------- split-K SGEMM (fp32, for M): atomicAdd, TRB wp2 ------------
template <int RELU_A, int TRB>
__global__ void __launch_bounds__(256) sgemm_sk(
    const float* __restrict__ A, const float* __restrict__ B,
    const float* __restrict__ bias, float* __restrict__ C,
    int M, int N, int K, int Ks, float* __restrict__ zout) {
    __shared__ float sA[16][36];
    __shared__ float sB[16][132];
    const int tid = threadIdx.x;
    const int tx = tid & 31, ty = tid >> 5;
    const int m0 = blockIdx.y * 32, n0 = blockIdx.x * 128;
    const int kbeg = blockIdx.z * Ks;

    if (zout != nullptr && blockIdx.y == 0 && blockIdx.z == 0) {
        int idx = blockIdx.x * 256 + tid;
        if (idx < 2 * NNODE * 4) zout[idx] = 0.f;
    }

    ull acc[8];
    #pragma unroll
    for (int i = 0; i < 8; ++i) acc[i] = 0ULL;

    for (int k0 = kbeg; k0 < kbeg + Ks; k0 += 16) {
        {
            int m = tid >> 3, kq = (tid & 7) * 2;
            float2 a = make_float2(0.f, 0.f);
            if (m0 + m < M) a = *(const float2*)(A + (size_t)(m0 + m) * K + k0 + kq);
            if (RELU_A) { a.x = fmaxf(a.x, 0.f); a.y = fmaxf(a.y, 0.f); }
            sA[kq][m] = a.x; sA[kq + 1][m] = a.y;
        }
        if (TRB == 0) {
            int k = tid >> 4, n8 = (tid & 15) * 8;
            const float* bp = B + (size_t)(k0 + k) * N + n0 + n8;
            float4 b0 = *(const float4*)(bp);
            float4 b1 = *(const float4*)(bp + 4);
            *(float4*)&sB[k][n8] = b0;
            *(float4*)&sB[k][n8 + 4] = b1;
        } else {
            int k = tid & 15, n8 = (tid >> 4) * 8;
            int i = k0 + k, j0 = n0 + n8;
            const float* bp = B + (size_t)(j0 >> 2) * 4096 + i * 4;
            float4 b0 = *(const float4*)(bp);
            float4 b1 = *(const float4*)(bp + 4096);
            *(float4*)&sB[k][n8] = b0;
            *(float4*)&sB[k][n8 + 4] = b1;
        }
        __syncthreads();
        #pragma unroll
        for (int k = 0; k < 16; ++k) {
            float4 av = *(const float4*)&sA[k][ty * 4];
            ulonglong2 bv = *(const ulonglong2*)&sB[k][tx * 4];
            ull a0 = pack2(av.x), a1 = pack2(av.y), a2 = pack2(av.z), a3 = pack2(av.w);
            ffma2(acc[0], a0, bv.x); ffma2(acc[1], a0, bv.y);
            ffma2(acc[2], a1, bv.x); ffma2(acc[3], a1, bv.y);
            ffma2(acc[4], a2, bv.x); ffma2(acc[5], a2, bv.y);
            ffma2(acc[6], a3, bv.x); ffma2(acc[7], a3, bv.y);
        }
        __syncthreads();
    }
    const bool addb = (bias != nullptr) && (blockIdx.z == 0);
    #pragma unroll
    for (int r = 0; r < 4; ++r) {
        int row = m0 + ty * 4 + r;
        if (row >= M) continue;
        float2 v01 = unpk(acc[r * 2]), v23 = unpk(acc[r * 2 + 1]);
        float v[4] = {v01.x, v01.y, v23.x, v23.y};
        int col = n0 + tx * 4;
        #pragma unroll
        for (int j = 0; j < 4; ++j) {
            float o = v[j];
            if (addb) o += bias[col + j];
            atomicAdd(&C[(size_t)row * N + col + j], o);
        }
    }
}

// ---------------- edge MLP with HMMA phase-2 (proven R13) --------------------
__global__ void __launch_bounds__(128) k_edge_mlp(
    const float* __restrict__ P, const float* __restrict__ Q,
    const float* __restrict__ pri,
    const float* __restrict__ be1,
    const float* __restrict__ be2,
    const float* __restrict__ we3, const float* __restrict__ be3,
    float* __restrict__ out_ea) {
    extern __shared__ __half s_dyn[];
    __half* s_wt = s_dyn;
    __half* s_h1 = s_dyn + 64 * 264;
    __shared__ float s_h2[TE][68];
    __shared__ float s_ea[TE][4];
    __shared__ int s_src[TE], s_dst[TE];

    const int t = threadIdx.x;
    const int e0 = blockIdx.x * TE;
    const int wid = t >> 5, lane = t & 31;

    if (t < TE) {
        int e = e0 + t;
        if (e >= NEDGE) e = NEDGE - 1;
        int i = e / 199;
        int r = e - i * 199;
        int j = (r < i) ? r : (r + 1);
        s_src[t] = i; s_dst[t] = j;
    }
    {
        const int4* src = (const int4*)g_wt;
        #pragma unroll
        for (int i = 0; i < 16; ++i) {
            int c = i * 128 + t;
            int n = c >> 5, kc = c & 31;
            *(int4*)(s_wt + n * 264 + kc * 8) = src[c];
        }
    }
    __syncthreads();

    #pragma unroll
    for (int l = 0; l < 32; ++l) {
        int idx = l * 128 + t;
        int el = idx >> 6, j4 = idx & 63;
        float4 p = ((const float4*)(P + s_src[el] * 256))[j4];
        float4 q = ((const float4*)(Q + s_dst[el] * 256))[j4];
        float4 b = ((const float4*)be1)[j4];
        __half2 h0 = __floats2half2_rn(fmaxf(p.x + q.x + b.x, 0.f),
                                       fmaxf(p.y + q.y + b.y, 0.f));
        __half2 h1 = __floats2half2_rn(fmaxf(p.z + q.z + b.z, 0.f),
                                       fmaxf(p.w + q.w + b.w, 0.f));
        __half2* dst = (__half2*)(s_h1 + el * 264 + j4 * 4);
        dst[0] = h0; dst[1] = h1;
    }
    __syncthreads();

    {
        const uint sAb = smem_u32(s_h1);
        const uint sWb = smem_u32(s_wt);
        const int aj = lane & 7, ag = lane >> 3;
        const uint a_off = (uint)(((ag & 1) * 8 + aj) * 528 + (ag >> 1) * 16);
        const int bj = lane & 7, bg = (lane >> 3) & 1;

        float D[4][2][4];
        #pragma unroll
        for (int mt = 0; mt < 4; ++mt)
            #pragma unroll
            for (int nt = 0; nt < 2; ++nt)
                #pragma unroll
                for (int i = 0; i < 4; ++i) D[mt][nt][i] = 0.f;

        #pragma unroll 4
        for (int ks = 0; ks < 16; ++ks) {
            uint a[4][4];
            #pragma unroll
            for (int mt = 0; mt < 4; ++mt) {
                uint addr = sAb + (uint)(mt * 16 * 528 + ks * 32) + a_off;
                asm volatile("ldmatrix.sync.aligned.m8n8.x4.shared.b16 "
                             "{%0,%1,%2,%3}, [%4];"
                             : "=r"(a[mt][0]), "=r"(a[mt][1]),
                               "=r"(a[mt][2]), "=r"(a[mt][3]) : "r"(addr));
            }
            #pragma unroll
            for (int nt = 0; nt < 2; ++nt) {
                uint b0, b1;
                uint baddr = sWb + (uint)((wid * 16 + nt * 8 + bj) * 528
                                          + ks * 32 + bg * 16);
                asm volatile("ldmatrix.sync.aligned.m8n8.x2.shared.b16 "
                             "{%0,%1}, [%2];" : "=r"(b0), "=r"(b1) : "r"(baddr));
                #pragma unroll
                for (int mt = 0; mt < 4; ++mt) {
                    asm volatile(
                        "mma.sync.aligned.m16n8k16.row.col.f32.f16.f16.f32 "
                        "{%0,%1,%2,%3}, {%4,%5,%6,%7}, {%8,%9}, {%0,%1,%2,%3};"
                        : "+f"(D[mt][nt][0]), "+f"(D[mt][nt][1]),
                          "+f"(D[mt][nt][2]), "+f"(D[mt][nt][3])
                        : "r"(a[mt][0]), "r"(a[mt][1]), "r"(a[mt][2]), "r"(a[mt][3]),
                          "r"(b0), "r"(b1));
                }
            }
        }

        const int r = lane >> 2, c = (lane & 3) * 2;
        #pragma unroll
        for (int mt = 0; mt < 4; ++mt)
            #pragma unroll
            for (int nt = 0; nt < 2; ++nt) {
                int n = wid * 16 + nt * 8 + c;
                float bc0 = be2[n], bc1 = be2[n + 1];
                int e = mt * 16 + r;
                s_h2[e][n]     = fmaxf(D[mt][nt][0] + bc0, 0.f);
                s_h2[e][n + 1] = fmaxf(D[mt][nt][1] + bc1, 0.f);
                s_h2[e + 8][n]     = fmaxf(D[mt][nt][2] + bc0, 0.f);
                s_h2[e + 8][n + 1] = fmaxf(D[mt][nt][3] + bc1, 0.f);
            }
    }
    __syncthreads();

    for (int idx = t; idx < 192; idx += 128) {
        int e = idx / 3, c = idx - (idx / 3) * 3;
        float s = be3[c];
        #pragma unroll 8
        for (int k = 0; k < 64; ++k) s += s_h2[e][k] * we3[k * 3 + c];
        s_ea[e][c] = 1.f / (1.f + __expf(-s));
    }
    if (t < TE) s_ea[t][3] = (pri[s_src[t]] > pri[s_dst[t]]) ? 1.f : 0.f;
    __syncthreads();

    #pragma unroll
    for (int l = 0; l < 2; ++l) {
        int idx = l * 128 + t;
        int e = idx >> 2, c = idx & 3;
        if (e0 + e < NEDGE) out_ea[(size_t)(e0 + e) * 4 + c] = s_ea[e][c];
    }
}

// -------- merged msg + vec + M-rezero: one block per src node ----------------
__global__ void __launch_bounds__(256) k_msgvec(
    const float* __restrict__ ea, float* __restrict__ Mn,
    const float* __restrict__ x,
    const float* __restrict__ wi, const float* __restrict__ bi,
    const float* __restrict__ bp2,
    const float* __restrict__ rw, const float* __restrict__ rb,
    const float* __restrict__ wp1, const float* __restrict__ bp1,
    float* __restrict__ out_expl, float* __restrict__ out_agg) {
    __shared__ float sM[512];
    __shared__ float swp[512];
    __shared__ float sbp[128];
    __shared__ float red[8][13];
    __shared__ float s_cv[4];
    const int src = blockIdx.x, t = threadIdx.x;

    sM[t] = Mn[src * 512 + t];
    sM[t + 256] = Mn[src * 512 + 256 + t];
    Mn[src * 512 + t] = 0.f;                 // re-zero for next execution
    Mn[src * 512 + 256 + t] = 0.f;
    swp[t] = wp1[t]; swp[t + 256] = wp1[t + 256];
    if (t < 128) sbp[t] = bp1[t];

    float4 xv = *(const float4*)(x + (size_t)src * NCH + t * 4);
    {
        float xa[4] = {xv.x, xv.y, xv.z, xv.w};
        float v[12];
        #pragma unroll
        for (int c = 0; c < 12; ++c) v[c] = 0.f;
        #pragma unroll
        for (int j = 0; j < 4; ++j) {
            int i = t * 4 + j;
            float xs = xa[j];
            float4 w0 = *(const float4*)(wi  + i * 4);
            float4 w1 = *(const float4*)(bp2 + i * 4);
            float4 w2 = *(const float4*)(rw  + i * 4);
            v[0] += xs * w0.x; v[1] += xs * w0.y; v[2]  += xs * w0.z; v[3]  += xs * w0.w;
            v[4] += xs * w1.x; v[5] += xs * w1.y; v[6]  += xs * w1.z; v[7]  += xs * w1.w;
            v[8] += xs * w2.x; v[9] += xs * w2.y; v[10] += xs * w2.z; v[11] += xs * w2.w;
        }
        #pragma unroll
        for (int s = 16; s; s >>= 1)
            #pragma unroll
            for (int c = 0; c < 12; ++c) v[c] += __shfl_xor_sync(0xffffffffu, v[c], s);
        if ((t & 31) == 0)
            #pragma unroll
            for (int c = 0; c < 12; ++c) red[t >> 5][c] = v[c];
    }
    __syncthreads();
    if (t < 12) {
        float s = 0.f;
        #pragma unroll
        for (int w = 0; w < 8; ++w) s += red[w][t];
        int o = t & 3;
        if (t < 4)      out_expl[src * 4 + o] = 1.f / (1.f + __expf(-(s + bi[o])));
        else if (t < 8) s_cv[o] = s;
        else            atomicAdd(&out_agg[src * 4 + o], s + rb[o]);
    }
    __syncthreads();

    float4 cv = *(const float4*)s_cv;
    const int slot = t >> 2, q = t & 3;
    for (int eb = 0; eb < 4; ++eb) {
        int el = eb * 64 + slot;
        if (el >= 199) break;
        int dst = el + (el >= src ? 1 : 0);
        int e = src * 199 + el;
        float4 eav = ((const float4*)ea)[e];
        float4 a = make_float4(0.f, 0.f, 0.f, 0.f);
        #pragma unroll 8
        for (int kk = 0; kk < 32; ++kk) {
            int k = kk * 4 + q;
            float h = sbp[k] + eav.x * swp[k] + eav.y * swp[128 + k]
                             + eav.z * swp[256 + k] + eav.w * swp[384 + k];
            h = fmaxf(h, 0.f);
            float4 m = ((const float4*)sM)[k];
            a.x += h * m.x; a.y += h * m.y; a.z += h * m.z; a.w += h * m.w;
        }
        #pragma unroll
        for (int s = 1; s < 4; s <<= 1) {
            a.x += __shfl_xor_sync(0xffffffffu, a.x, s);
            a.y += __shfl_xor_sync(0xffffffffu, a.y, s);
            a.z += __shfl_xor_sync(0xffffffffu, a.z, s);
            a.w += __shfl_xor_sync(0xffffffffu, a.w, s);
        }
        if (q == 0) {
            atomicAdd(&out_agg[dst * 4 + 0], a.x + cv.x);
            atomicAdd(&out_agg[dst * 4 + 1], a.y + cv.y);
            atomicAdd(&out_agg[dst * 4 + 2], a.z + cv.z);
            atomicAdd(&out_agg[dst * 4 + 3], a.w + cv.w);
        }
    }
}

// ---------------- launch ----------------
extern "C" void kernel_launch(void* const* d_in, const int* in_sizes, int n_in,
                              void* d_out, int out_size) {
    const float* roi  = (const float*)d_in[0];
    const float* bbox = (const float*)d_in[1];
    const float* dir  = (const float*)d_in[2];
    const float* pri  = (const float*)d_in[3];
    const float* w1  = (const float*)d_in[4];  const float* b1  = (const float*)d_in[5];
    const float* w2  = (const float*)d_in[6];  const float* b2  = (const float*)d_in[7];
    const float* w3  = (const float*)d_in[8];  const float* b3  = (const float*)d_in[9];
    const float* wi  = (const float*)d_in[10]; const float* bi  = (const float*)d_in[11];
    const float* we1 = (const float*)d_in[12]; const float* be1 = (const float*)d_in[13];
    const float* we2 = (const float*)d_in[14]; const float* be2 = (const float*)d_in[15];
    const float* we3 = (const float*)d_in[16]; const float* be3 = (const float*)d_in[17];
    const float* wp1 = (const float*)d_in[18]; const float* bp1 = (const float*)d_in[19];
    const float* wp2 = (const float*)d_in[20]; const float* bp2 = (const float*)d_in[21];
    const float* rw  = (const float*)d_in[22]; const float* rb  = (const float*)d_in[23];
    float* out = (float*)d_out;

    float* scr;
    cudaGetSymbolAddress((void**)&scr, g_scr);
    float* p_x = scr + OFF_X;
    float* p_M = scr + OFF_M;
    float* p_P = scr + OFF_P;
    float* p_Q = scr + OFF_Q;

    static cudaStream_t s2 = nullptr;
    static cudaEvent_t evF = nullptr, ev2 = nullptr;
    if (!s2) {
        cudaStreamCreateWithFlags(&s2, cudaStreamNonBlocking);
        cudaEventCreateWithFlags(&evF, cudaEventDisableTiming);
        cudaEventCreateWithFlags(&ev2, cudaEventDisableTiming);
        cudaFuncSetAttribute(k_edge_mlp,
                             cudaFuncAttributeMaxDynamicSharedMemorySize,
                             2 * 64 * 264 * (int)sizeof(__half));
        cudaFuncSetAttribute(k_fused,
                             cudaFuncAttributeMaxDynamicSharedMemorySize,
                             FUSED_SMEM);
    }

    // fork edge branch (uses the many SMs k_fused leaves idle)
    cudaEventRecord(evF, 0);
    cudaStreamWaitEvent(s2, evF, 0);
    k_pq<<<dim3(2, NNODE), 128, 0, s2>>>(bbox, dir, we1, we2, p_P, p_Q);
    k_edge_mlp<<<EBLK, 128, 2 * 64 * 264 * sizeof(__half), s2>>>(
        p_P, p_Q, pri, be1, be2, we3, be3, out + 1600);
    cudaEventRecord(ev2, s2);

    // main chain (stream 0): 3 nodes
    k_fused<<<13, 256, FUSED_SMEM, 0>>>(roi, w1, b1, w2, b2, w3, b3, p_x);
    sgemm_sk<0,1><<<dim3(4, 7, 8), 256, 0, 0>>>(p_x, wp2, (const float*)nullptr, p_M,
                                                NNODE, 512, NCH, 128, out);
    cudaStreamWaitEvent(0, ev2, 0);
    k_msgvec<<<NNODE, 256, 0, 0>>>(out + 1600, p_M, p_x,
                                   wi, bi, bp2, rw, rb, wp1, bp1,
                                   out + 800, out);
}

// round 15
// speedup vs baseline: 1.3798x; 1.3798x over previous
#include <cuda_runtime.h>
#include <cuda_fp16.h>
#include <math.h>

typedef unsigned long long ull;
typedef unsigned int uint;

// ---------------- problem constants ----------------
#define NNODE 200
#define IMGF  2048
#define HD1   512
#define HD2   256
#define NCH   1024
#define NEDGE 39800
#define TE    64
#define EBLK  622

// ---------------- f32x2 helpers ----------------
__device__ __forceinline__ ull pack2(float a) {
    ull r; asm("mov.b64 %0,{%1,%1};" : "=l"(r) : "f"(a)); return r;
}
__device__ __forceinline__ void ffma2(ull& acc, ull a, ull b) {
    asm("fma.rn.f32x2 %0,%1,%2,%0;" : "+l"(acc) : "l"(a), "l"(b));
}
__device__ __forceinline__ float2 unpk(ull v) {
    float2 r; asm("mov.b64 {%0,%1},%2;" : "=f"(r.x), "=f"(r.y) : "l"(v)); return r;
}

// ---------------- device scratch ----------------
// h1 and M receive atomicAdds; k_msgvec re-zeroes both at the END of every
// execution (device globals start zeroed; invariant holds across replays).
// x is fully overwritten by k_g23 each execution.
#define OFF_H1   0
#define OFF_X    (OFF_H1 + NNODE*HD1)
#define OFF_M    (OFF_X  + NNODE*NCH)
#define OFF_P    (OFF_M  + NNODE*512)
#define OFF_Q    (OFF_P + NNODE*256)
#define SCR_TOTAL (OFF_Q + NNODE*256)
__device__ float g_scr[SCR_TOTAL];
__device__ __half g_wt[64 * 256];       // we2^T fp16 [n][k] for edge kernel

__device__ __forceinline__ uint smem_u32(const void* p) {
    uint a;
    asm("{ .reg .u64 t; cvta.to.shared.u64 t, %1; cvt.u32.u64 %0, t; }"
        : "=r"(a) : "l"(p));
    return a;
}

// P/Q precompute + we2^T fp16 conversion
__global__ void k_pq(const float* __restrict__ bbox, const float* __restrict__ dirs,
                     const float* __restrict__ we1, const float* __restrict__ we2,
                     float* __restrict__ P, float* __restrict__ Q) {
    __shared__ float a[8];
    int n = blockIdx.y, j = blockIdx.x * 128 + threadIdx.x;
    if (threadIdx.x < 8) {
        int c = threadIdx.x;
        a[c] = (c < 4) ? bbox[n * 4 + c] * (1.0f / 1024.0f) : dirs[n * 4 + c - 4];
    }
    if (blockIdx.x == 0 && blockIdx.y < 8) {
        int base = (blockIdx.y * 128 + threadIdx.x) * 16;
        #pragma unroll
        for (int i = 0; i < 16; ++i) {
            int m = base + i;
            int nn = m >> 8, k = m & 255;
            g_wt[m] = __float2half(we2[k * 64 + nn]);
        }
    }
    __syncthreads();
    float p = 0.f, q = 0.f;
    #pragma unroll
    for (int c = 0; c < 8; ++c) {
        p += a[c] * we1[c * 256 + j];
        q += a[c] * we1[(c + 8) * 256 + j];
    }
    P[n * 256 + j] = p;
    Q[n * 256 + j] = q;
}

// ---------------- split-K SGEMM (fp32): atomicAdd, split 0 adds bias ---------
template <int RELU_A, int TRB>
__global__ void __launch_bounds__(256) sgemm_sk(
    const float* __restrict__ A, const float* __restrict__ B,
    const float* __restrict__ bias, float* __restrict__ C,
    int M, int N, int K, int Ks, float* __restrict__ zout) {
    __shared__ float sA[16][36];
    __shared__ float sB[16][132];
    const int tid = threadIdx.x;
    const int tx = tid & 31, ty = tid >> 5;
    const int m0 = blockIdx.y * 32, n0 = blockIdx.x * 128;
    const int kbeg = blockIdx.z * Ks;

    if (zout != nullptr && blockIdx.y == 0 && blockIdx.z == 0) {
        int idx = blockIdx.x * 256 + tid;
        if (idx < 2 * NNODE * 4) zout[idx] = 0.f;
    }

    ull acc[8];
    #pragma unroll
    for (int i = 0; i < 8; ++i) acc[i] = 0ULL;

    for (int k0 = kbeg; k0 < kbeg + Ks; k0 += 16) {
        {
            int m = tid >> 3, kq = (tid & 7) * 2;
            float2 a = make_float2(0.f, 0.f);
            if (m0 + m < M) a = *(const float2*)(A + (size_t)(m0 + m) * K + k0 + kq);
            if (RELU_A) { a.x = fmaxf(a.x, 0.f); a.y = fmaxf(a.y, 0.f); }
            sA[kq][m] = a.x; sA[kq + 1][m] = a.y;
        }
        if (TRB == 0) {
            int k = tid >> 4, n8 = (tid & 15) * 8;
            const float* bp = B + (size_t)(k0 + k) * N + n0 + n8;
            float4 b0 = *(const float4*)(bp);
            float4 b1 = *(const float4*)(bp + 4);
            *(float4*)&sB[k][n8] = b0;
            *(float4*)&sB[k][n8 + 4] = b1;
        } else {
            int k = tid & 15, n8 = (tid >> 4) * 8;
            int i = k0 + k, j0 = n0 + n8;
            const float* bp = B + (size_t)(j0 >> 2) * 4096 + i * 4;
            float4 b0 = *(const float4*)(bp);
            float4 b1 = *(const float4*)(bp + 4096);
            *(float4*)&sB[k][n8] = b0;
            *(float4*)&sB[k][n8 + 4] = b1;
        }
        __syncthreads();
        #pragma unroll
        for (int k = 0; k < 16; ++k) {
            float4 av = *(const float4*)&sA[k][ty * 4];
            ulonglong2 bv = *(const ulonglong2*)&sB[k][tx * 4];
            ull a0 = pack2(av.x), a1 = pack2(av.y), a2 = pack2(av.z), a3 = pack2(av.w);
            ffma2(acc[0], a0, bv.x); ffma2(acc[1], a0, bv.y);
            ffma2(acc[2], a1, bv.x); ffma2(acc[3], a1, bv.y);
            ffma2(acc[4], a2, bv.x); ffma2(acc[5], a2, bv.y);
            ffma2(acc[6], a3, bv.x); ffma2(acc[7], a3, bv.y);
        }
        __syncthreads();
    }
    const bool addb = (bias != nullptr) && (blockIdx.z == 0);
    #pragma unroll
    for (int r = 0; r < 4; ++r) {
        int row = m0 + ty * 4 + r;
        if (row >= M) continue;
        float2 v01 = unpk(acc[r * 2]), v23 = unpk(acc[r * 2 + 1]);
        float v[4] = {v01.x, v01.y, v23.x, v23.y};
        int col = n0 + tx * 4;
        #pragma unroll
        for (int j = 0; j < 4; ++j) {
            float o = v[j];
            if (addb) o += bias[col + j];
            atomicAdd(&C[(size_t)row * N + col + j], o);
        }
    }
}

// ------------- fused g2+g3 (HMMA): h1 -> h2 -> x-half -----------------------
// grid (13, 2): x-tile of 16 rows, n-half of layer 3. 256 threads (8 warps).
// smem halfs: sB[64][520] | sH1[16][520] | sH2[16][264]
#define G23_SB  (64 * 520)
#define G23_SH1 (16 * 520)
#define G23_SH2 (16 * 264)
#define G23_SMEM ((G23_SB + G23_SH1 + G23_SH2) * 2)

__global__ void __launch_bounds__(256) k_g23(
    const float* __restrict__ h1g,
    const float* __restrict__ w2, const float* __restrict__ b2,
    const float* __restrict__ w3, const float* __restrict__ b3,
    float* __restrict__ xo) {
    extern __shared__ __half sdyn[];
    __half* sB  = sdyn;
    __half* sH1 = sdyn + G23_SB;
    __half* sH2 = sH1 + G23_SH1;

    const int t = threadIdx.x, wid = t >> 5, lane = t & 31;
    const int m0 = blockIdx.x * 16, nh = blockIdx.y;
    const uint sBb = smem_u32(sB), sH1b = smem_u32(sH1), sH2b = smem_u32(sH2);
    const int aj = lane & 7, ag = lane >> 3;
    const uint arow = (uint)((ag & 1) * 8 + aj);
    const uint acol = (uint)((ag >> 1) * 16);
    const int kr16 = lane & 15;
    const int r = lane >> 2, c2 = (lane & 3) * 2;

    // stage h1 tile: relu(h1[m0..+16][0..512]) fp32 -> fp16 smem
    #pragma unroll
    for (int i = 0; i < 8; ++i) {
        int idx = i * 256 + t;              // 16 rows x 128 float4
        int row = idx >> 7, c4 = (idx & 127) * 4;
        float4 v = make_float4(0.f, 0.f, 0.f, 0.f);
        if (m0 + row < NNODE)
            v = *(const float4*)(h1g + (size_t)(m0 + row) * HD1 + c4);
        __half2* p = (__half2*)(sH1 + row * 520 + c4);
        p[0] = __floats2half2_rn(fmaxf(v.x, 0.f), fmaxf(v.y, 0.f));
        p[1] = __floats2half2_rn(fmaxf(v.z, 0.f), fmaxf(v.w, 0.f));
    }
    __syncthreads();

    // ---- layer 2: h2[16][256] = relu(h1) @ w2 + b2 (proven R14 body) ----
    {
        float D[4][4];
        #pragma unroll
        for (int nf = 0; nf < 4; ++nf)
            #pragma unroll
            for (int i = 0; i < 4; ++i) D[nf][i] = 0.f;

        for (int k0 = 0; k0 < HD1; k0 += 64) {
            #pragma unroll 8
            for (int i = 0; i < 16; ++i) {
                int e4 = i * 256 + t;
                int kr = e4 >> 6, nc4 = (e4 & 63) * 4;
                float4 v = *(const float4*)(w2 + (size_t)(k0 + kr) * HD2 + nc4);
                __half2* p = (__half2*)(sB + kr * 520 + nc4);
                p[0] = __floats2half2_rn(v.x, v.y);
                p[1] = __floats2half2_rn(v.z, v.w);
            }
            __syncthreads();
            #pragma unroll
            for (int ks = 0; ks < 4; ++ks) {
                uint a[4];
                uint addr = sH1b + arow * 1040 + (uint)((k0 + ks * 16) * 2) + acol;
                asm volatile("ldmatrix.sync.aligned.m8n8.x4.shared.b16 "
                             "{%0,%1,%2,%3}, [%4];"
                             : "=r"(a[0]), "=r"(a[1]), "=r"(a[2]), "=r"(a[3])
                             : "r"(addr));
                #pragma unroll
                for (int nf = 0; nf < 4; ++nf) {
                    uint b0, b1v;
                    uint baddr = sBb + (uint)((ks * 16 + kr16) * 1040
                                              + (wid * 32 + nf * 8) * 2);
                    asm volatile("ldmatrix.sync.aligned.m8n8.x2.trans.shared.b16 "
                                 "{%0,%1}, [%2];" : "=r"(b0), "=r"(b1v) : "r"(baddr));
                    asm volatile(
                        "mma.sync.aligned.m16n8k16.row.col.f32.f16.f16.f32 "
                        "{%0,%1,%2,%3}, {%4,%5,%6,%7}, {%8,%9}, {%0,%1,%2,%3};"
                        : "+f"(D[nf][0]), "+f"(D[nf][1]), "+f"(D[nf][2]), "+f"(D[nf][3])
                        : "r"(a[0]), "r"(a[1]), "r"(a[2]), "r"(a[3]),
                          "r"(b0), "r"(b1v));
                }
            }
            __syncthreads();
        }
        #pragma unroll
        for (int nf = 0; nf < 4; ++nf) {
            int n = wid * 32 + nf * 8 + c2;
            float bb0 = b2[n], bb1 = b2[n + 1];
            *(__half2*)(sH2 + r * 264 + n) =
                __floats2half2_rn(fmaxf(D[nf][0] + bb0, 0.f), fmaxf(D[nf][1] + bb1, 0.f));
            *(__half2*)(sH2 + (r + 8) * 264 + n) =
                __floats2half2_rn(fmaxf(D[nf][2] + bb0, 0.f), fmaxf(D[nf][3] + bb1, 0.f));
        }
        __syncthreads();
    }

    // ---- layer 3: x[16][nh*512..+512] = h2 @ w3 + b3 (proven R14 body) ----
    {
        float D[8][4];
        #pragma unroll
        for (int nf = 0; nf < 8; ++nf)
            #pragma unroll
            for (int i = 0; i < 4; ++i) D[nf][i] = 0.f;

        for (int k0 = 0; k0 < HD2; k0 += 64) {
            #pragma unroll 8
            for (int i = 0; i < 32; ++i) {
                int e4 = i * 256 + t;
                int kr = e4 >> 7, nc4 = (e4 & 127) * 4;
                float4 v = *(const float4*)(w3 + (size_t)(k0 + kr) * NCH + nh * 512 + nc4);
                __half2* p = (__half2*)(sB + kr * 520 + nc4);
                p[0] = __floats2half2_rn(v.x, v.y);
                p[1] = __floats2half2_rn(v.z, v.w);
            }
            __syncthreads();
            #pragma unroll
            for (int ks = 0; ks < 4; ++ks) {
                uint a[4];
                uint addr = sH2b + arow * 528 + (uint)((k0 + ks * 16) * 2) + acol;
                asm volatile("ldmatrix.sync.aligned.m8n8.x4.shared.b16 "
                             "{%0,%1,%2,%3}, [%4];"
                             : "=r"(a[0]), "=r"(a[1]), "=r"(a[2]), "=r"(a[3])
                             : "r"(addr));
                #pragma unroll
                for (int nf = 0; nf < 8; ++nf) {
                    uint b0, b1v;
                    uint baddr = sBb + (uint)((ks * 16 + kr16) * 1040
                                              + (wid * 64 + nf * 8) * 2);
                    asm volatile("ldmatrix.sync.aligned.m8n8.x2.trans.shared.b16 "
                                 "{%0,%1}, [%2];" : "=r"(b0), "=r"(b1v) : "r"(baddr));
                    asm volatile(
                        "mma.sync.aligned.m16n8k16.row.col.f32.f16.f16.f32 "
                        "{%0,%1,%2,%3}, {%4,%5,%6,%7}, {%8,%9}, {%0,%1,%2,%3};"
                        : "+f"(D[nf][0]), "+f"(D[nf][1]), "+f"(D[nf][2]), "+f"(D[nf][3])
                        : "r"(a[0]), "r"(a[1]), "r"(a[2]), "r"(a[3]),
                          "r"(b0), "r"(b1v));
                }
            }
            __syncthreads();
        }
        int row0 = m0 + r, row1 = m0 + r + 8;
        #pragma unroll
        for (int nf = 0; nf < 8; ++nf) {
            int n = nh * 512 + wid * 64 + nf * 8 + c2;
            float bb0 = b3[n], bb1 = b3[n + 1];
            if (row0 < NNODE) {
                xo[(size_t)row0 * NCH + n] = D[nf][0] + bb0;
                xo[(size_t)row0 * NCH + n + 1] = D[nf][1] + bb1;
            }
            if (row1 < NNODE) {
                xo[(size_t)row1 * NCH + n] = D[nf][2] + bb0;
                xo[(size_t)row1 * NCH + n + 1] = D[nf][3] + bb1;
            }
        }
    }
}

// ---------------- edge MLP with HMMA phase-2 (proven R13) --------------------
__global__ void __launch_bounds__(128) k_edge_mlp(
    const float* __restrict__ P, const float* __restrict__ Q,
    const float* __restrict__ pri,
    const float* __restrict__ be1,
    const float* __restrict__ be2,
    const float* __restrict__ we3, const float* __restrict__ be3,
    float* __restrict__ out_ea) {
    extern __shared__ __half s_dyn[];
    __half* s_wt = s_dyn;
    __half* s_h1 = s_dyn + 64 * 264;
    __shared__ float s_h2[TE][68];
    __shared__ float s_ea[TE][4];
    __shared__ int s_src[TE], s_dst[TE];

    const int t = threadIdx.x;
    const int e0 = blockIdx.x * TE;
    const int wid = t >> 5, lane = t & 31;

    if (t < TE) {
        int e = e0 + t;
        if (e >= NEDGE) e = NEDGE - 1;
        int i = e / 199;
        int r = e - i * 199;
        int j = (r < i) ? r : (r + 1);
        s_src[t] = i; s_dst[t] = j;
    }
    {
        const int4* src = (const int4*)g_wt;
        #pragma unroll
        for (int i = 0; i < 16; ++i) {
            int c = i * 128 + t;
            int n = c >> 5, kc = c & 31;
            *(int4*)(s_wt + n * 264 + kc * 8) = src[c];
        }
    }
    __syncthreads();

    #pragma unroll
    for (int l = 0; l < 32; ++l) {
        int idx = l * 128 + t;
        int el = idx >> 6, j4 = idx & 63;
        float4 p = ((const float4*)(P + s_src[el] * 256))[j4];
        float4 q = ((const float4*)(Q + s_dst[el] * 256))[j4];
        float4 b = ((const float4*)be1)[j4];
        __half2 h0 = __floats2half2_rn(fmaxf(p.x + q.x + b.x, 0.f),
                                       fmaxf(p.y + q.y + b.y, 0.f));
        __half2 h1 = __floats2half2_rn(fmaxf(p.z + q.z + b.z, 0.f),
                                       fmaxf(p.w + q.w + b.w, 0.f));
        __half2* dst = (__half2*)(s_h1 + el * 264 + j4 * 4);
        dst[0] = h0; dst[1] = h1;
    }
    __syncthreads();

    {
        const uint sAb = smem_u32(s_h1);
        const uint sWb = smem_u32(s_wt);
        const int aj = lane & 7, ag = lane >> 3;
        const uint a_off = (uint)(((ag & 1) * 8 + aj) * 528 + (ag >> 1) * 16);
        const int bj = lane & 7, bg = (lane >> 3) & 1;

        float D[4][2][4];
        #pragma unroll
        for (int mt = 0; mt < 4; ++mt)
            #pragma unroll
            for (int nt = 0; nt < 2; ++nt)
                #pragma unroll
                for (int i = 0; i < 4; ++i) D[mt][nt][i] = 0.f;

        #pragma unroll 4
        for (int ks = 0; ks < 16; ++ks) {
            uint a[4][4];
            #pragma unroll
            for (int mt = 0; mt < 4; ++mt) {
                uint addr = sAb + (uint)(mt * 16 * 528 + ks * 32) + a_off;
                asm volatile("ldmatrix.sync.aligned.m8n8.x4.shared.b16 "
                             "{%0,%1,%2,%3}, [%4];"
                             : "=r"(a[mt][0]), "=r"(a[mt][1]),
                               "=r"(a[mt][2]), "=r"(a[mt][3]) : "r"(addr));
            }
            #pragma unroll
            for (int nt = 0; nt < 2; ++nt) {
                uint b0, b1;
                uint baddr = sWb + (uint)((wid * 16 + nt * 8 + bj) * 528
                                          + ks * 32 + bg * 16);
                asm volatile("ldmatrix.sync.aligned.m8n8.x2.shared.b16 "
                             "{%0,%1}, [%2];" : "=r"(b0), "=r"(b1) : "r"(baddr));
                #pragma unroll
                for (int mt = 0; mt < 4; ++mt) {
                    asm volatile(
                        "mma.sync.aligned.m16n8k16.row.col.f32.f16.f16.f32 "
                        "{%0,%1,%2,%3}, {%4,%5,%6,%7}, {%8,%9}, {%0,%1,%2,%3};"
                        : "+f"(D[mt][nt][0]), "+f"(D[mt][nt][1]),
                          "+f"(D[mt][nt][2]), "+f"(D[mt][nt][3])
                        : "r"(a[mt][0]), "r"(a[mt][1]), "r"(a[mt][2]), "r"(a[mt][3]),
                          "r"(b0), "r"(b1));
                }
            }
        }

        const int r = lane >> 2, c = (lane & 3) * 2;
        #pragma unroll
        for (int mt = 0; mt < 4; ++mt)
            #pragma unroll
            for (int nt = 0; nt < 2; ++nt) {
                int n = wid * 16 + nt * 8 + c;
                float bc0 = be2[n], bc1 = be2[n + 1];
                int e = mt * 16 + r;
                s_h2[e][n]     = fmaxf(D[mt][nt][0] + bc0, 0.f);
                s_h2[e][n + 1] = fmaxf(D[mt][nt][1] + bc1, 0.f);
                s_h2[e + 8][n]     = fmaxf(D[mt][nt][2] + bc0, 0.f);
                s_h2[e + 8][n + 1] = fmaxf(D[mt][nt][3] + bc1, 0.f);
            }
    }
    __syncthreads();

    for (int idx = t; idx < 192; idx += 128) {
        int e = idx / 3, c = idx - (idx / 3) * 3;
        float s = be3[c];
        #pragma unroll 8
        for (int k = 0; k < 64; ++k) s += s_h2[e][k] * we3[k * 3 + c];
        s_ea[e][c] = 1.f / (1.f + __expf(-s));
    }
    if (t < TE) s_ea[t][3] = (pri[s_src[t]] > pri[s_dst[t]]) ? 1.f : 0.f;
    __syncthreads();

    #pragma unroll
    for (int l = 0; l < 2; ++l) {
        int idx = l * 128 + t;
        int e = idx >> 2, c = idx & 3;
        if (e0 + e < NEDGE) out_ea[(size_t)(e0 + e) * 4 + c] = s_ea[e][c];
    }
}

// -------- merged msg + vec + scratch-rezero (h1, M) --------------------------
__global__ void __launch_bounds__(256) k_msgvec(
    const float* __restrict__ ea, float* __restrict__ Mn,
    const float* __restrict__ x, float* __restrict__ h1z,
    const float* __restrict__ wi, const float* __restrict__ bi,
    const float* __restrict__ bp2,
    const float* __restrict__ rw, const float* __restrict__ rb,
    const float* __restrict__ wp1, const float* __restrict__ bp1,
    float* __restrict__ out_expl, float* __restrict__ out_agg) {
    __shared__ float sM[512];
    __shared__ float swp[512];
    __shared__ float sbp[128];
    __shared__ float red[8][13];
    __shared__ float s_cv[4];
    const int src = blockIdx.x, t = threadIdx.x;
    const float4 z4 = make_float4(0.f, 0.f, 0.f, 0.f);

    sM[t] = Mn[src * 512 + t];
    sM[t + 256] = Mn[src * 512 + 256 + t];
    Mn[src * 512 + t] = 0.f;
    Mn[src * 512 + 256 + t] = 0.f;
    swp[t] = wp1[t]; swp[t + 256] = wp1[t + 256];
    if (t < 128) sbp[t] = bp1[t];

    float4 xv = *(const float4*)(x + (size_t)src * NCH + t * 4);
    {
        float xa[4] = {xv.x, xv.y, xv.z, xv.w};
        float v[12];
        #pragma unroll
        for (int c = 0; c < 12; ++c) v[c] = 0.f;
        #pragma unroll
        for (int j = 0; j < 4; ++j) {
            int i = t * 4 + j;
            float xs = xa[j];
            float4 w0 = *(const float4*)(wi  + i * 4);
            float4 w1 = *(const float4*)(bp2 + i * 4);
            float4 w2 = *(const float4*)(rw  + i * 4);
            v[0] += xs * w0.x; v[1] += xs * w0.y; v[2]  += xs * w0.z; v[3]  += xs * w0.w;
            v[4] += xs * w1.x; v[5] += xs * w1.y; v[6]  += xs * w1.z; v[7]  += xs * w1.w;
            v[8] += xs * w2.x; v[9] += xs * w2.y; v[10] += xs * w2.z; v[11] += xs * w2.w;
        }
        #pragma unroll
        for (int s = 16; s; s >>= 1)
            #pragma unroll
            for (int c = 0; c < 12; ++c) v[c] += __shfl_xor_sync(0xffffffffu, v[c], s);
        if ((t & 31) == 0)
            #pragma unroll
            for (int c = 0; c < 12; ++c) red[t >> 5][c] = v[c];
    }
    // re-zero h1 slice: 102400 floats / 200 blocks = 128 float4 per block
    if (t < 128) ((float4*)h1z)[src * 128 + t] = z4;
    __syncthreads();
    if (t < 12) {
        float s = 0.f;
        #pragma unroll
        for (int w = 0; w < 8; ++w) s += red[w][t];
        int o = t & 3;
        if (t < 4)      out_expl[src * 4 + o] = 1.f / (1.f + __expf(-(s + bi[o])));
        else if (t < 8) s_cv[o] = s;
        else            atomicAdd(&out_agg[src * 4 + o], s + rb[o]);
    }
    __syncthreads();

    float4 cv = *(const float4*)s_cv;
    const int slot = t >> 2, q = t & 3;
    for (int eb = 0; eb < 4; ++eb) {
        int el = eb * 64 + slot;
        if (el >= 199) break;
        int dst = el + (el >= src ? 1 : 0);
        int e = src * 199 + el;
        float4 eav = ((const float4*)ea)[e];
        float4 a = make_float4(0.f, 0.f, 0.f, 0.f);
        #pragma unroll 8
        for (int kk = 0; kk < 32; ++kk) {
            int k = kk * 4 + q;
            float h = sbp[k] + eav.x * swp[k] + eav.y * swp[128 + k]
                             + eav.z * swp[256 + k] + eav.w * swp[384 + k];
            h = fmaxf(h, 0.f);
            float4 m = ((const float4*)sM)[k];
            a.x += h * m.x; a.y += h * m.y; a.z += h * m.z; a.w += h * m.w;
        }
        #pragma unroll
        for (int s = 1; s < 4; s <<= 1) {
            a.x += __shfl_xor_sync(0xffffffffu, a.x, s);
            a.y += __shfl_xor_sync(0xffffffffu, a.y, s);
            a.z += __shfl_xor_sync(0xffffffffu, a.z, s);
            a.w += __shfl_xor_sync(0xffffffffu, a.w, s);
        }
        if (q == 0) {
            atomicAdd(&out_agg[dst * 4 + 0], a.x + cv.x);
            atomicAdd(&out_agg[dst * 4 + 1], a.y + cv.y);
            atomicAdd(&out_agg[dst * 4 + 2], a.z + cv.z);
            atomicAdd(&out_agg[dst * 4 + 3], a.w + cv.w);
        }
    }
}

// ---------------- launch ----------------
extern "C" void kernel_launch(void* const* d_in, const int* in_sizes, int n_in,
                              void* d_out, int out_size) {
    const float* roi  = (const float*)d_in[0];
    const float* bbox = (const float*)d_in[1];
    const float* dir  = (const float*)d_in[2];
    const float* pri  = (const float*)d_in[3];
    const float* w1  = (const float*)d_in[4];  const float* b1  = (const float*)d_in[5];
    const float* w2  = (const float*)d_in[6];  const float* b2  = (const float*)d_in[7];
    const float* w3  = (const float*)d_in[8];  const float* b3  = (const float*)d_in[9];
    const float* wi  = (const float*)d_in[10]; const float* bi  = (const float*)d_in[11];
    const float* we1 = (const float*)d_in[12]; const float* be1 = (const float*)d_in[13];
    const float* we2 = (const float*)d_in[14]; const float* be2 = (const float*)d_in[15];
    const float* we3 = (const float*)d_in[16]; const float* be3 = (const float*)d_in[17];
    const float* wp1 = (const float*)d_in[18]; const float* bp1 = (const float*)d_in[19];
    const float* wp2 = (const float*)d_in[20]; const float* bp2 = (const float*)d_in[21];
    const float* rw  = (const float*)d_in[22]; const float* rb  = (const float*)d_in[23];
    float* out = (float*)d_out;

    float* scr;
    cudaGetSymbolAddress((void**)&scr, g_scr);
    float* p_h1 = scr + OFF_H1;
    float* p_x  = scr + OFF_X;
    float* p_M  = scr + OFF_M;
    float* p_P  = scr + OFF_P;
    float* p_Q  = scr + OFF_Q;

    static cudaStream_t s2 = nullptr;
    static cudaEvent_t evF = nullptr, ev2 = nullptr;
    if (!s2) {
        cudaStreamCreateWithFlags(&s2, cudaStreamNonBlocking);
        cudaEventCreateWithFlags(&evF, cudaEventDisableTiming);
        cudaEventCreateWithFlags(&ev2, cudaEventDisableTiming);
        cudaFuncSetAttribute(k_edge_mlp,
                             cudaFuncAttributeMaxDynamicSharedMemorySize,
                             2 * 64 * 264 * (int)sizeof(__half));
        cudaFuncSetAttribute(k_g23,
                             cudaFuncAttributeMaxDynamicSharedMemorySize,
                             G23_SMEM);
    }

    // fork edge branch
    cudaEventRecord(evF, 0);
    cudaStreamWaitEvent(s2, evF, 0);
    k_pq<<<dim3(2, NNODE), 128, 0, s2>>>(bbox, dir, we1, we2, p_P, p_Q);
    k_edge_mlp<<<EBLK, 128, 2 * 64 * 264 * sizeof(__half), s2>>>(
        p_P, p_Q, pri, be1, be2, we3, be3, out + 1600);
    cudaEventRecord(ev2, s2);

    // main chain (stream 0): 4 nodes
    sgemm_sk<0,0><<<dim3(4, 7, 8), 256, 0, 0>>>(roi, w1, b1, p_h1,
                                                NNODE, HD1, IMGF, 256, nullptr);
    k_g23<<<dim3(13, 2), 256, G23_SMEM, 0>>>(p_h1, w2, b2, w3, b3, p_x);
    sgemm_sk<0,1><<<dim3(4, 7, 8), 256, 0, 0>>>(p_x, wp2, (const float*)nullptr, p_M,
                                                NNODE, 512, NCH, 128, out);
    cudaStreamWaitEvent(0, ev2, 0);
    k_msgvec<<<NNODE, 256, 0, 0>>>(out + 1600, p_M, p_x, p_h1,
                                   wi, bi, bp2, rw, rb, wp1, bp1,
                                   out + 800, out);
}

// round 16
// speedup vs baseline: 1.4400x; 1.0437x over previous
#include <cuda_runtime.h>
#include <cuda_fp16.h>
#include <math.h>

typedef unsigned long long ull;
typedef unsigned int uint;

// ---------------- problem constants ----------------
#define NNODE 200
#define IMGF  2048
#define HD1   512
#define HD2   256
#define NCH   1024
#define NEDGE 39800
#define TE    64
#define EBLK  622

// ---------------- f32x2 helpers ----------------
__device__ __forceinline__ ull pack2(float a) {
    ull r; asm("mov.b64 %0,{%1,%1};" : "=l"(r) : "f"(a)); return r;
}
__device__ __forceinline__ void ffma2(ull& acc, ull a, ull b) {
    asm("fma.rn.f32x2 %0,%1,%2,%0;" : "+l"(acc) : "l"(a), "l"(b));
}
__device__ __forceinline__ float2 unpk(ull v) {
    float2 r; asm("mov.b64 {%0,%1},%2;" : "=f"(r.x), "=f"(r.y) : "l"(v)); return r;
}

// ---------------- device scratch ----------------
// h1 and M receive atomicAdds; k_msgvec re-zeroes both at the END of every
// execution (device globals start zeroed; invariant holds across replays).
// x is fully overwritten by k_g23 each execution.
#define OFF_H1   0
#define OFF_X    (OFF_H1 + NNODE*HD1)
#define OFF_M    (OFF_X  + NNODE*NCH)
#define OFF_P    (OFF_M  + NNODE*512)
#define OFF_Q    (OFF_P + NNODE*256)
#define SCR_TOTAL (OFF_Q + NNODE*256)
__device__ float g_scr[SCR_TOTAL];
__device__ __half g_wt[64 * 256];        // we2^T fp16 [n][k] for edge kernel
__device__ __half g_w2h[HD1 * HD2];      // w2 fp16 (k-major, same layout)
__device__ __half g_w3h[HD2 * NCH];      // w3 fp16 (k-major, same layout)

__device__ __forceinline__ uint smem_u32(const void* p) {
    uint a;
    asm("{ .reg .u64 t; cvta.to.shared.u64 t, %1; cvt.u32.u64 %0, t; }"
        : "=r"(a) : "l"(p));
    return a;
}

// P/Q precompute + we2^T fp16 conversion
__global__ void k_pq(const float* __restrict__ bbox, const float* __restrict__ dirs,
                     const float* __restrict__ we1, const float* __restrict__ we2,
                     float* __restrict__ P, float* __restrict__ Q) {
    __shared__ float a[8];
    int n = blockIdx.y, j = blockIdx.x * 128 + threadIdx.x;
    if (threadIdx.x < 8) {
        int c = threadIdx.x;
        a[c] = (c < 4) ? bbox[n * 4 + c] * (1.0f / 1024.0f) : dirs[n * 4 + c - 4];
    }
    if (blockIdx.x == 0 && blockIdx.y < 8) {
        int base = (blockIdx.y * 128 + threadIdx.x) * 16;
        #pragma unroll
        for (int i = 0; i < 16; ++i) {
            int m = base + i;
            int nn = m >> 8, k = m & 255;
            g_wt[m] = __float2half(we2[k * 64 + nn]);
        }
    }
    __syncthreads();
    float p = 0.f, q = 0.f;
    #pragma unroll
    for (int c = 0; c < 8; ++c) {
        p += a[c] * we1[c * 256 + j];
        q += a[c] * we1[(c + 8) * 256 + j];
    }
    P[n * 256 + j] = p;
    Q[n * 256 + j] = q;
}

// ---------------- split-K SGEMM (fp32): atomicAdd, split 0 adds bias ---------
// cvt2/cvt3 non-null: all blocks cooperatively convert w2/w3 fp32->fp16
// (spread over the whole grid; ~1.7K elements per block -> negligible).
template <int RELU_A, int TRB>
__global__ void __launch_bounds__(256) sgemm_sk(
    const float* __restrict__ A, const float* __restrict__ B,
    const float* __restrict__ bias, float* __restrict__ C,
    int M, int N, int K, int Ks, float* __restrict__ zout,
    const float* __restrict__ cvt2s, __half* __restrict__ cvt2d,
    const float* __restrict__ cvt3s, __half* __restrict__ cvt3d) {
    __shared__ float sA[16][36];
    __shared__ float sB[16][132];
    const int tid = threadIdx.x;
    const int tx = tid & 31, ty = tid >> 5;
    const int m0 = blockIdx.y * 32, n0 = blockIdx.x * 128;
    const int kbeg = blockIdx.z * Ks;

    if (cvt2d != nullptr) {
        int gb = blockIdx.x + gridDim.x * (blockIdx.y + gridDim.y * blockIdx.z);
        int gt = gb * 256 + tid;
        int tot = gridDim.x * gridDim.y * gridDim.z * 256;
        for (int i = gt; i < HD1 * HD2; i += tot) cvt2d[i] = __float2half(cvt2s[i]);
        for (int i = gt; i < HD2 * NCH; i += tot) cvt3d[i] = __float2half(cvt3s[i]);
    }
    if (zout != nullptr && blockIdx.y == 0 && blockIdx.z == 0) {
        int idx = blockIdx.x * 256 + tid;
        if (idx < 2 * NNODE * 4) zout[idx] = 0.f;
    }

    ull acc[8];
    #pragma unroll
    for (int i = 0; i < 8; ++i) acc[i] = 0ULL;

    for (int k0 = kbeg; k0 < kbeg + Ks; k0 += 16) {
        {
            int m = tid >> 3, kq = (tid & 7) * 2;
            float2 a = make_float2(0.f, 0.f);
            if (m0 + m < M) a = *(const float2*)(A + (size_t)(m0 + m) * K + k0 + kq);
            if (RELU_A) { a.x = fmaxf(a.x, 0.f); a.y = fmaxf(a.y, 0.f); }
            sA[kq][m] = a.x; sA[kq + 1][m] = a.y;
        }
        if (TRB == 0) {
            int k = tid >> 4, n8 = (tid & 15) * 8;
            const float* bp = B + (size_t)(k0 + k) * N + n0 + n8;
            float4 b0 = *(const float4*)(bp);
            float4 b1 = *(const float4*)(bp + 4);
            *(float4*)&sB[k][n8] = b0;
            *(float4*)&sB[k][n8 + 4] = b1;
        } else {
            int k = tid & 15, n8 = (tid >> 4) * 8;
            int i = k0 + k, j0 = n0 + n8;
            const float* bp = B + (size_t)(j0 >> 2) * 4096 + i * 4;
            float4 b0 = *(const float4*)(bp);
            float4 b1 = *(const float4*)(bp + 4096);
            *(float4*)&sB[k][n8] = b0;
            *(float4*)&sB[k][n8 + 4] = b1;
        }
        __syncthreads();
        #pragma unroll
        for (int k = 0; k < 16; ++k) {
            float4 av = *(const float4*)&sA[k][ty * 4];
            ulonglong2 bv = *(const ulonglong2*)&sB[k][tx * 4];
            ull a0 = pack2(av.x), a1 = pack2(av.y), a2 = pack2(av.z), a3 = pack2(av.w);
            ffma2(acc[0], a0, bv.x); ffma2(acc[1], a0, bv.y);
            ffma2(acc[2], a1, bv.x); ffma2(acc[3], a1, bv.y);
            ffma2(acc[4], a2, bv.x); ffma2(acc[5], a2, bv.y);
            ffma2(acc[6], a3, bv.x); ffma2(acc[7], a3, bv.y);
        }
        __syncthreads();
    }
    const bool addb = (bias != nullptr) && (blockIdx.z == 0);
    #pragma unroll
    for (int r = 0; r < 4; ++r) {
        int row = m0 + ty * 4 + r;
        if (row >= M) continue;
        float2 v01 = unpk(acc[r * 2]), v23 = unpk(acc[r * 2 + 1]);
        float v[4] = {v01.x, v01.y, v23.x, v23.y};
        int col = n0 + tx * 4;
        #pragma unroll
        for (int j = 0; j < 4; ++j) {
            float o = v[j];
            if (addb) o += bias[col + j];
            atomicAdd(&C[(size_t)row * N + col + j], o);
        }
    }
}

// ------------- fused g2+g3 (HMMA, pre-converted fp16 weights) ---------------
// grid (13, 2): x-tile of 16 rows, n-half of layer 3. 256 threads (8 warps).
// smem halfs: sB[64][520] | sH1[16][520] | sH2[16][264]
#define G23_SB  (64 * 520)
#define G23_SH1 (16 * 520)
#define G23_SH2 (16 * 264)
#define G23_SMEM ((G23_SB + G23_SH1 + G23_SH2) * 2)

__global__ void __launch_bounds__(256) k_g23(
    const float* __restrict__ h1g,
    const float* __restrict__ b2, const float* __restrict__ b3,
    float* __restrict__ xo) {
    extern __shared__ __half sdyn[];
    __half* sB  = sdyn;
    __half* sH1 = sdyn + G23_SB;
    __half* sH2 = sH1 + G23_SH1;

    const int t = threadIdx.x, wid = t >> 5, lane = t & 31;
    const int m0 = blockIdx.x * 16, nh = blockIdx.y;
    const uint sBb = smem_u32(sB), sH1b = smem_u32(sH1), sH2b = smem_u32(sH2);
    const int aj = lane & 7, ag = lane >> 3;
    const uint arow = (uint)((ag & 1) * 8 + aj);
    const uint acol = (uint)((ag >> 1) * 16);
    const int kr16 = lane & 15;
    const int r = lane >> 2, c2 = (lane & 3) * 2;

    // stage h1 tile: relu(h1[m0..+16][0..512]) fp32 -> fp16 smem (small)
    #pragma unroll
    for (int i = 0; i < 8; ++i) {
        int idx = i * 256 + t;
        int row = idx >> 7, c4 = (idx & 127) * 4;
        float4 v = make_float4(0.f, 0.f, 0.f, 0.f);
        if (m0 + row < NNODE)
            v = *(const float4*)(h1g + (size_t)(m0 + row) * HD1 + c4);
        __half2* p = (__half2*)(sH1 + row * 520 + c4);
        p[0] = __floats2half2_rn(fmaxf(v.x, 0.f), fmaxf(v.y, 0.f));
        p[1] = __floats2half2_rn(fmaxf(v.z, 0.f), fmaxf(v.w, 0.f));
    }
    __syncthreads();

    // ---- layer 2: h2[16][256] = relu(h1) @ w2 + b2 ----
    {
        float D[4][4];
        #pragma unroll
        for (int nf = 0; nf < 4; ++nf)
            #pragma unroll
            for (int i = 0; i < 4; ++i) D[nf][i] = 0.f;

        for (int k0 = 0; k0 < HD1; k0 += 64) {
            // stage pre-converted w2 fp16: 64 rows x 32 int4 = 2048 / 256 thr
            #pragma unroll
            for (int i = 0; i < 8; ++i) {
                int c = i * 256 + t;
                int kr = c >> 5, kc = c & 31;
                *(int4*)(sB + kr * 520 + kc * 8) =
                    ((const int4*)(g_w2h + (size_t)(k0 + kr) * HD2))[kc];
            }
            __syncthreads();
            #pragma unroll
            for (int ks = 0; ks < 4; ++ks) {
                uint a[4];
                uint addr = sH1b + arow * 1040 + (uint)((k0 + ks * 16) * 2) + acol;
                asm volatile("ldmatrix.sync.aligned.m8n8.x4.shared.b16 "
                             "{%0,%1,%2,%3}, [%4];"
                             : "=r"(a[0]), "=r"(a[1]), "=r"(a[2]), "=r"(a[3])
                             : "r"(addr));
                #pragma unroll
                for (int nf = 0; nf < 4; ++nf) {
                    uint b0, b1v;
                    uint baddr = sBb + (uint)((ks * 16 + kr16) * 1040
                                              + (wid * 32 + nf * 8) * 2);
                    asm volatile("ldmatrix.sync.aligned.m8n8.x2.trans.shared.b16 "
                                 "{%0,%1}, [%2];" : "=r"(b0), "=r"(b1v) : "r"(baddr));
                    asm volatile(
                        "mma.sync.aligned.m16n8k16.row.col.f32.f16.f16.f32 "
                        "{%0,%1,%2,%3}, {%4,%5,%6,%7}, {%8,%9}, {%0,%1,%2,%3};"
                        : "+f"(D[nf][0]), "+f"(D[nf][1]), "+f"(D[nf][2]), "+f"(D[nf][3])
                        : "r"(a[0]), "r"(a[1]), "r"(a[2]), "r"(a[3]),
                          "r"(b0), "r"(b1v));
                }
            }
            __syncthreads();
        }
        #pragma unroll
        for (int nf = 0; nf < 4; ++nf) {
            int n = wid * 32 + nf * 8 + c2;
            float bb0 = b2[n], bb1 = b2[n + 1];
            *(__half2*)(sH2 + r * 264 + n) =
                __floats2half2_rn(fmaxf(D[nf][0] + bb0, 0.f), fmaxf(D[nf][1] + bb1, 0.f));
            *(__half2*)(sH2 + (r + 8) * 264 + n) =
                __floats2half2_rn(fmaxf(D[nf][2] + bb0, 0.f), fmaxf(D[nf][3] + bb1, 0.f));
        }
        __syncthreads();
    }

    // ---- layer 3: x[16][nh*512..+512] = h2 @ w3 + b3 ----
    {
        float D[8][4];
        #pragma unroll
        for (int nf = 0; nf < 8; ++nf)
            #pragma unroll
            for (int i = 0; i < 4; ++i) D[nf][i] = 0.f;

        for (int k0 = 0; k0 < HD2; k0 += 64) {
            // stage pre-converted w3 fp16: 64 rows x 64 int4 = 4096 / 256 thr
            #pragma unroll
            for (int i = 0; i < 16; ++i) {
                int c = i * 256 + t;
                int kr = c >> 6, kc = c & 63;
                *(int4*)(sB + kr * 520 + kc * 8) =
                    ((const int4*)(g_w3h + (size_t)(k0 + kr) * NCH + nh * 512))[kc];
            }
            __syncthreads();
            #pragma unroll
            for (int ks = 0; ks < 4; ++ks) {
                uint a[4];
                uint addr = sH2b + arow * 528 + (uint)((k0 + ks * 16) * 2) + acol;
                asm volatile("ldmatrix.sync.aligned.m8n8.x4.shared.b16 "
                             "{%0,%1,%2,%3}, [%4];"
                             : "=r"(a[0]), "=r"(a[1]), "=r"(a[2]), "=r"(a[3])
                             : "r"(addr));
                #pragma unroll
                for (int nf = 0; nf < 8; ++nf) {
                    uint b0, b1v;
                    uint baddr = sBb + (uint)((ks * 16 + kr16) * 1040
                                              + (wid * 64 + nf * 8) * 2);
                    asm volatile("ldmatrix.sync.aligned.m8n8.x2.trans.shared.b16 "
                                 "{%0,%1}, [%2];" : "=r"(b0), "=r"(b1v) : "r"(baddr));
                    asm volatile(
                        "mma.sync.aligned.m16n8k16.row.col.f32.f16.f16.f32 "
                        "{%0,%1,%2,%3}, {%4,%5,%6,%7}, {%8,%9}, {%0,%1,%2,%3};"
                        : "+f"(D[nf][0]), "+f"(D[nf][1]), "+f"(D[nf][2]), "+f"(D[nf][3])
                        : "r"(a[0]), "r"(a[1]), "r"(a[2]), "r"(a[3]),
                          "r"(b0), "r"(b1v));
                }
            }
            __syncthreads();
        }
        int row0 = m0 + r, row1 = m0 + r + 8;
        #pragma unroll
        for (int nf = 0; nf < 8; ++nf) {
            int n = nh * 512 + wid * 64 + nf * 8 + c2;
            float bb0 = b3[n], bb1 = b3[n + 1];
            if (row0 < NNODE) {
                xo[(size_t)row0 * NCH + n] = D[nf][0] + bb0;
                xo[(size_t)row0 * NCH + n + 1] = D[nf][1] + bb1;
            }
            if (row1 < NNODE) {
                xo[(size_t)row1 * NCH + n] = D[nf][2] + bb0;
                xo[(size_t)row1 * NCH + n + 1] = D[nf][3] + bb1;
            }
        }
    }
}

// ---------------- edge MLP with HMMA phase-2 (proven R13) --------------------
__global__ void __launch_bounds__(128) k_edge_mlp(
    const float* __restrict__ P, const float* __restrict__ Q,
    const float* __restrict__ pri,
    const float* __restrict__ be1,
    const float* __restrict__ be2,
    const float* __restrict__ we3, const float* __restrict__ be3,
    float* __restrict__ out_ea) {
    extern __shared__ __half s_dyn[];
    __half* s_wt = s_dyn;
    __half* s_h1 = s_dyn + 64 * 264;
    __shared__ float s_h2[TE][68];
    __shared__ float s_ea[TE][4];
    __shared__ int s_src[TE], s_dst[TE];

    const int t = threadIdx.x;
    const int e0 = blockIdx.x * TE;
    const int wid = t >> 5, lane = t & 31;

    if (t < TE) {
        int e = e0 + t;
        if (e >= NEDGE) e = NEDGE - 1;
        int i = e / 199;
        int r = e - i * 199;
        int j = (r < i) ? r : (r + 1);
        s_src[t] = i; s_dst[t] = j;
    }
    {
        const int4* src = (const int4*)g_wt;
        #pragma unroll
        for (int i = 0; i < 16; ++i) {
            int c = i * 128 + t;
            int n = c >> 5, kc = c & 31;
            *(int4*)(s_wt + n * 264 + kc * 8) = src[c];
        }
    }
    __syncthreads();

    #pragma unroll
    for (int l = 0; l < 32; ++l) {
        int idx = l * 128 + t;
        int el = idx >> 6, j4 = idx & 63;
        float4 p = ((const float4*)(P + s_src[el] * 256))[j4];
        float4 q = ((const float4*)(Q + s_dst[el] * 256))[j4];
        float4 b = ((const float4*)be1)[j4];
        __half2 h0 = __floats2half2_rn(fmaxf(p.x + q.x + b.x, 0.f),
                                       fmaxf(p.y + q.y + b.y, 0.f));
        __half2 h1 = __floats2half2_rn(fmaxf(p.z + q.z + b.z, 0.f),
                                       fmaxf(p.w + q.w + b.w, 0.f));
        __half2* dst = (__half2*)(s_h1 + el * 264 + j4 * 4);
        dst[0] = h0; dst[1] = h1;
    }
    __syncthreads();

    {
        const uint sAb = smem_u32(s_h1);
        const uint sWb = smem_u32(s_wt);
        const int aj = lane & 7, ag = lane >> 3;
        const uint a_off = (uint)(((ag & 1) * 8 + aj) * 528 + (ag >> 1) * 16);
        const int bj = lane & 7, bg = (lane >> 3) & 1;

        float D[4][2][4];
        #pragma unroll
        for (int mt = 0; mt < 4; ++mt)
            #pragma unroll
            for (int nt = 0; nt < 2; ++nt)
                #pragma unroll
                for (int i = 0; i < 4; ++i) D[mt][nt][i] = 0.f;

        #pragma unroll 4
        for (int ks = 0; ks < 16; ++ks) {
            uint a[4][4];
            #pragma unroll
            for (int mt = 0; mt < 4; ++mt) {
                uint addr = sAb + (uint)(mt * 16 * 528 + ks * 32) + a_off;
                asm volatile("ldmatrix.sync.aligned.m8n8.x4.shared.b16 "
                             "{%0,%1,%2,%3}, [%4];"
                             : "=r"(a[mt][0]), "=r"(a[mt][1]),
                               "=r"(a[mt][2]), "=r"(a[mt][3]) : "r"(addr));
            }
            #pragma unroll
            for (int nt = 0; nt < 2; ++nt) {
                uint b0, b1;
                uint baddr = sWb + (uint)((wid * 16 + nt * 8 + bj) * 528
                                          + ks * 32 + bg * 16);
                asm volatile("ldmatrix.sync.aligned.m8n8.x2.shared.b16 "
                             "{%0,%1}, [%2];" : "=r"(b0), "=r"(b1) : "r"(baddr));
                #pragma unroll
                for (int mt = 0; mt < 4; ++mt) {
                    asm volatile(
                        "mma.sync.aligned.m16n8k16.row.col.f32.f16.f16.f32 "
                        "{%0,%1,%2,%3}, {%4,%5,%6,%7}, {%8,%9}, {%0,%1,%2,%3};"
                        : "+f"(D[mt][nt][0]), "+f"(D[mt][nt][1]),
                          "+f"(D[mt][nt][2]), "+f"(D[mt][nt][3])
                        : "r"(a[mt][0]), "r"(a[mt][1]), "r"(a[mt][2]), "r"(a[mt][3]),
                          "r"(b0), "r"(b1));
                }
            }
        }

        const int r = lane >> 2, c = (lane & 3) * 2;
        #pragma unroll
        for (int mt = 0; mt < 4; ++mt)
            #pragma unroll
            for (int nt = 0; nt < 2; ++nt) {
                int n = wid * 16 + nt * 8 + c;
                float bc0 = be2[n], bc1 = be2[n + 1];
                int e = mt * 16 + r;
                s_h2[e][n]     = fmaxf(D[mt][nt][0] + bc0, 0.f);
                s_h2[e][n + 1] = fmaxf(D[mt][nt][1] + bc1, 0.f);
                s_h2[e + 8][n]     = fmaxf(D[mt][nt][2] + bc0, 0.f);
                s_h2[e + 8][n + 1] = fmaxf(D[mt][nt][3] + bc1, 0.f);
            }
    }
    __syncthreads();

    for (int idx = t; idx < 192; idx += 128) {
        int e = idx / 3, c = idx - (idx / 3) * 3;
        float s = be3[c];
        #pragma unroll 8
        for (int k = 0; k < 64; ++k) s += s_h2[e][k] * we3[k * 3 + c];
        s_ea[e][c] = 1.f / (1.f + __expf(-s));
    }
    if (t < TE) s_ea[t][3] = (pri[s_src[t]] > pri[s_dst[t]]) ? 1.f : 0.f;
    __syncthreads();

    #pragma unroll
    for (int l = 0; l < 2; ++l) {
        int idx = l * 128 + t;
        int e = idx >> 2, c = idx & 3;
        if (e0 + e < NEDGE) out_ea[(size_t)(e0 + e) * 4 + c] = s_ea[e][c];
    }
}

// -------- merged msg + vec + scratch-rezero (h1, M) --------------------------
__global__ void __launch_bounds__(256) k_msgvec(
    const float* __restrict__ ea, float* __restrict__ Mn,
    const float* __restrict__ x, float* __restrict__ h1z,
    const float* __restrict__ wi, const float* __restrict__ bi,
    const float* __restrict__ bp2,
    const float* __restrict__ rw, const float* __restrict__ rb,
    const float* __restrict__ wp1, const float* __restrict__ bp1,
    float* __restrict__ out_expl, float* __restrict__ out_agg) {
    __shared__ float sM[512];
    __shared__ float swp[512];
    __shared__ float sbp[128];
    __shared__ float red[8][13];
    __shared__ float s_cv[4];
    const int src = blockIdx.x, t = threadIdx.x;
    const float4 z4 = make_float4(0.f, 0.f, 0.f, 0.f);

    sM[t] = Mn[src * 512 + t];
    sM[t + 256] = Mn[src * 512 + 256 + t];
    Mn[src * 512 + t] = 0.f;
    Mn[src * 512 + 256 + t] = 0.f;
    swp[t] = wp1[t]; swp[t + 256] = wp1[t + 256];
    if (t < 128) sbp[t] = bp1[t];

    float4 xv = *(const float4*)(x + (size_t)src * NCH + t * 4);
    {
        float xa[4] = {xv.x, xv.y, xv.z, xv.w};
        float v[12];
        #pragma unroll
        for (int c = 0; c < 12; ++c) v[c] = 0.f;
        #pragma unroll
        for (int j = 0; j < 4; ++j) {
            int i = t * 4 + j;
            float xs = xa[j];
            float4 w0 = *(const float4*)(wi  + i * 4);
            float4 w1 = *(const float4*)(bp2 + i * 4);
            float4 w2 = *(const float4*)(rw  + i * 4);
            v[0] += xs * w0.x; v[1] += xs * w0.y; v[2]  += xs * w0.z; v[3]  += xs * w0.w;
            v[4] += xs * w1.x; v[5] += xs * w1.y; v[6]  += xs * w1.z; v[7]  += xs * w1.w;
            v[8] += xs * w2.x; v[9] += xs * w2.y; v[10] += xs * w2.z; v[11] += xs * w2.w;
        }
        #pragma unroll
        for (int s = 16; s; s >>= 1)
            #pragma unroll
            for (int c = 0; c < 12; ++c) v[c] += __shfl_xor_sync(0xffffffffu, v[c], s);
        if ((t & 31) == 0)
            #pragma unroll
            for (int c = 0; c < 12; ++c) red[t >> 5][c] = v[c];
    }
    if (t < 128) ((float4*)h1z)[src * 128 + t] = z4;
    __syncthreads();
    if (t < 12) {
        float s = 0.f;
        #pragma unroll
        for (int w = 0; w < 8; ++w) s += red[w][t];
        int o = t & 3;
        if (t < 4)      out_expl[src * 4 + o] = 1.f / (1.f + __expf(-(s + bi[o])));
        else if (t < 8) s_cv[o] = s;
        else            atomicAdd(&out_agg[src * 4 + o], s + rb[o]);
    }
    __syncthreads();

    float4 cv = *(const float4*)s_cv;
    const int slot = t >> 2, q = t & 3;
    for (int eb = 0; eb < 4; ++eb) {
        int el = eb * 64 + slot;
        if (el >= 199) break;
        int dst = el + (el >= src ? 1 : 0);
        int e = src * 199 + el;
        float4 eav = ((const float4*)ea)[e];
        float4 a = make_float4(0.f, 0.f, 0.f, 0.f);
        #pragma unroll 8
        for (int kk = 0; kk < 32; ++kk) {
            int k = kk * 4 + q;
            float h = sbp[k] + eav.x * swp[k] + eav.y * swp[128 + k]
                             + eav.z * swp[256 + k] + eav.w * swp[384 + k];
            h = fmaxf(h, 0.f);
            float4 m = ((const float4*)sM)[k];
            a.x += h * m.x; a.y += h * m.y; a.z += h * m.z; a.w += h * m.w;
        }
        #pragma unroll
        for (int s = 1; s < 4; s <<= 1) {
            a.x += __shfl_xor_sync(0xffffffffu, a.x, s);
            a.y += __shfl_xor_sync(0xffffffffu, a.y, s);
            a.z += __shfl_xor_sync(0xffffffffu, a.z, s);
            a.w += __shfl_xor_sync(0xffffffffu, a.w, s);
        }
        if (q == 0) {
            atomicAdd(&out_agg[dst * 4 + 0], a.x + cv.x);
            atomicAdd(&out_agg[dst * 4 + 1], a.y + cv.y);
            atomicAdd(&out_agg[dst * 4 + 2], a.z + cv.z);
            atomicAdd(&out_agg[dst * 4 + 3], a.w + cv.w);
        }
    }
}

// ---------------- launch ----------------
extern "C" void kernel_launch(void* const* d_in, const int* in_sizes, int n_in,
                              void* d_out, int out_size) {
    const float* roi  = (const float*)d_in[0];
    const float* bbox = (const float*)d_in[1];
    const float* dir  = (const float*)d_in[2];
    const float* pri  = (const float*)d_in[3];
    const float* w1  = (const float*)d_in[4];  const float* b1  = (const float*)d_in[5];
    const float* w2  = (const float*)d_in[6];  const float* b2  = (const float*)d_in[7];
    const float* w3  = (const float*)d_in[8];  const float* b3  = (const float*)d_in[9];
    const float* wi  = (const float*)d_in[10]; const float* bi  = (const float*)d_in[11];
    const float* we1 = (const float*)d_in[12]; const float* be1 = (const float*)d_in[13];
    const float* we2 = (const float*)d_in[14]; const float* be2 = (const float*)d_in[15];
    const float* we3 = (const float*)d_in[16]; const float* be3 = (const float*)d_in[17];
    const float* wp1 = (const float*)d_in[18]; const float* bp1 = (const float*)d_in[19];
    const float* wp2 = (const float*)d_in[20]; const float* bp2 = (const float*)d_in[21];
    const float* rw  = (const float*)d_in[22]; const float* rb  = (const float*)d_in[23];
    float* out = (float*)d_out;

    float* scr;
    cudaGetSymbolAddress((void**)&scr, g_scr);
    float* p_h1 = scr + OFF_H1;
    float* p_x  = scr + OFF_X;
    float* p_M  = scr + OFF_M;
    float* p_P  = scr + OFF_P;
    float* p_Q  = scr + OFF_Q;
    __half *p_w2h, *p_w3h;
    cudaGetSymbolAddress((void**)&p_w2h, g_w2h);
    cudaGetSymbolAddress((void**)&p_w3h, g_w3h);

    static cudaStream_t s2 = nullptr;
    static cudaEvent_t evF = nullptr, ev2 = nullptr;
    if (!s2) {
        cudaStreamCreateWithFlags(&s2, cudaStreamNonBlocking);
        cudaEventCreateWithFlags(&evF, cudaEventDisableTiming);
        cudaEventCreateWithFlags(&ev2, cudaEventDisableTiming);
        cudaFuncSetAttribute(k_edge_mlp,
                             cudaFuncAttributeMaxDynamicSharedMemorySize,
                             2 * 64 * 264 * (int)sizeof(__half));
        cudaFuncSetAttribute(k_g23,
                             cudaFuncAttributeMaxDynamicSharedMemorySize,
                             G23_SMEM);
    }

    // fork edge branch
    cudaEventRecord(evF, 0);
    cudaStreamWaitEvent(s2, evF, 0);
    k_pq<<<dim3(2, NNODE), 128, 0, s2>>>(bbox, dir, we1, we2, p_P, p_Q);
    k_edge_mlp<<<EBLK, 128, 2 * 64 * 264 * sizeof(__half), s2>>>(
        p_P, p_Q, pri, be1, be2, we3, be3, out + 1600);
    cudaEventRecord(ev2, s2);

    // main chain (stream 0): 4 nodes
    // g1 also pre-converts w2/w3 to fp16 (spread over its 224 blocks)
    sgemm_sk<0,0><<<dim3(4, 7, 8), 256, 0, 0>>>(roi, w1, b1, p_h1,
                                                NNODE, HD1, IMGF, 256, nullptr,
                                                w2, p_w2h, w3, p_w3h);
    k_g23<<<dim3(13, 2), 256, G23_SMEM, 0>>>(p_h1, b2, b3, p_x);
    sgemm_sk<0,1><<<dim3(4, 7, 8), 256, 0, 0>>>(p_x, wp2, (const float*)nullptr, p_M,
                                                NNODE, 512, NCH, 128, out,
                                                (const float*)nullptr, (__half*)nullptr,
                                                (const float*)nullptr, (__half*)nullptr);
    cudaStreamWaitEvent(0, ev2, 0);
    k_msgvec<<<NNODE, 256, 0, 0>>>(out + 1600, p_M, p_x, p_h1,
                                   wi, bi, bp2, rw, rb, wp1, bp1,
                                   out + 800, out);
}